// round 16
// baseline (speedup 1.0000x reference)
#include <cuda_runtime.h>
#include <cstdint>

// Bidirectional tanh-Elman RNN, B=32, S=2048, D=H=256, fp32.
//
// rnn_kernel: R14 body verbatim (the only rnn arrangement that holds 1052us).
// xp_kernel : 128-thread CTAs, one (dir, timestep) tile each, s-major output,
//             prefix-ordered publication via g_prog[dir].
// The two kernels run CONCURRENTLY via a graph fork (events + second stream);
// xp hides in rnn's ~72% idle issue slots. rnn gates its xp prefetch on the
// monotonic g_prog counter (acquire-load only when behind).

#define S_SZ 2048
#define H_SZ 256
#define B_SZ 32

__device__ float g_xp[2u * 65536u * 256u];   // [dir][s*32 + b][j]  (s-major!)
__device__ unsigned g_prog[2];               // published tiles per dir (prefix)

__device__ __forceinline__ unsigned long long pack2(float a, float b) {
    unsigned long long r;
    asm("mov.b64 %0, {%1, %2};" : "=l"(r)
        : "r"(__float_as_uint(a)), "r"(__float_as_uint(b)));
    return r;
}
__device__ __forceinline__ void unpack2(unsigned long long p, float& a, float& b) {
    unsigned int lo, hi;
    asm("mov.b64 {%0, %1}, %2;" : "=r"(lo), "=r"(hi) : "l"(p));
    a = __uint_as_float(lo);
    b = __uint_as_float(hi);
}
__device__ __forceinline__ unsigned long long splat2(float a) {
    unsigned long long r;
    asm("mov.b64 %0, {%1, %1};" : "=l"(r) : "r"(__float_as_uint(a)));
    return r;
}
#define FMA2(acc, a, b) \
    asm("fma.rn.f32x2 %0, %1, %2, %0;" : "+l"(acc) : "l"(a), "l"(b))

__device__ __forceinline__ float fast_tanh(float z) {
    float e = __expf(2.0f * z);
    return 1.0f - __fdividef(2.0f, e + 1.0f);
}

__global__ void reset_kernel() {
    if (threadIdx.x < 2) g_prog[threadIdx.x] = 0u;
}

// ---------------------------------------------------------------------------
// xp producer: one CTA = one (dir, s) tile: 32 b x 256 j, K = 256.
// blockIdx.x = g: dir = g&1, p = g>>1, s = dir ? 2047-p : p  (consumption order)
// ---------------------------------------------------------------------------
#define SX_PITCH 36                       // floats; 144B, 16B-aligned rows
#define XP_SMEM_BYTES (64 * 256 * 4 + 256 * SX_PITCH * 4)   // sW + sX = 102400

__global__ __launch_bounds__(128, 1) void xp_kernel(
    const float* __restrict__ x,
    const float* __restrict__ Wx_f, const float* __restrict__ b_f,
    const float* __restrict__ Wx_b, const float* __restrict__ b_b)
{
    extern __shared__ float sm[];
    float* sW = sm;                       // [64][256] current K-chunk of W
    float* sX = sm + 64 * 256;            // [256][SX_PITCH] x_t transposed

    const int g   = blockIdx.x;
    const int dir = g & 1;
    const int p   = g >> 1;
    const int s   = dir ? (S_SZ - 1 - p) : p;
    const float* W    = dir ? Wx_b : Wx_f;
    const float* bias = dir ? b_b  : b_f;
    const int t  = threadIdx.x;
    const int jp = t;                     // cols jp and jp+128

    // stage x[b][s][:] transposed -> sX[k][b]
    {
        int b  = t >> 2;
        int kq = (t & 3) * 64;
        const float* xr = x + ((size_t)b * S_SZ + s) * 256 + kq;
        #pragma unroll
        for (int i = 0; i < 16; ++i) {
            float4 v = *(const float4*)(xr + 4 * i);
            int k = kq + 4 * i;
            sX[(k + 0) * SX_PITCH + b] = v.x;
            sX[(k + 1) * SX_PITCH + b] = v.y;
            sX[(k + 2) * SX_PITCH + b] = v.z;
            sX[(k + 3) * SX_PITCH + b] = v.w;
        }
    }

    unsigned long long accA[16], accB[16];   // acc[i] = b rows (2i, 2i+1)
    {
        unsigned long long ba = splat2(bias[jp]);
        unsigned long long bb = splat2(bias[jp + 128]);
        #pragma unroll
        for (int i = 0; i < 16; ++i) { accA[i] = ba; accB[i] = bb; }
    }
    __syncthreads();

    for (int c = 0; c < 4; ++c) {
        // stage W chunk [64 k][256 j]
        #pragma unroll
        for (int r = 0; r < 32; ++r) {
            int f4 = r * 128 + t;                 // 4096 float4s
            int kk = f4 >> 6, jj = (f4 & 63) * 4;
            *(float4*)(sW + kk * 256 + jj) =
                *(const float4*)(W + (c * 64 + kk) * H_SZ + jj);
        }
        __syncthreads();
        for (int k = 0; k < 64; ++k) {
            unsigned long long wa = splat2(sW[k * 256 + jp]);
            unsigned long long wb = splat2(sW[k * 256 + jp + 128]);
            const ulonglong2* xv = (const ulonglong2*)(sX + (c * 64 + k) * SX_PITCH);
            #pragma unroll
            for (int q = 0; q < 8; ++q) {
                ulonglong2 v = xv[q];             // b 4q..4q+3 (broadcast)
                FMA2(accA[2*q + 0], v.x, wa);
                FMA2(accA[2*q + 1], v.y, wa);
                FMA2(accB[2*q + 0], v.x, wb);
                FMA2(accB[2*q + 1], v.y, wb);
            }
        }
        __syncthreads();
    }

    // store tile: rows s*32 + b
    float* dst = g_xp + ((size_t)dir * 65536u + (size_t)s * 32u) * 256u;
    #pragma unroll
    for (int i = 0; i < 16; ++i) {
        float a0, a1, b0, b1;
        unpack2(accA[i], a0, a1);
        unpack2(accB[i], b0, b1);
        dst[(2*i + 0) * 256 + jp]       = a0;
        dst[(2*i + 1) * 256 + jp]       = a1;
        dst[(2*i + 0) * 256 + jp + 128] = b0;
        dst[(2*i + 1) * 256 + jp + 128] = b1;
    }
    __threadfence();
    __syncthreads();

    // prefix-ordered publish: wait for tile p-1, then announce p
    if (t == 0) {
        volatile unsigned* prog = (volatile unsigned*)&g_prog[dir];
        while (*prog != (unsigned)p) __nanosleep(64);
        *prog = (unsigned)(p + 1);
    }
}

// ---------------------------------------------------------------------------
// Phase 2: recurrence (R14 body; xp prefetch gated on g_prog).
// ---------------------------------------------------------------------------
__device__ __forceinline__ uint32_t smem_u32(const void* p) {
    uint32_t a;
    asm("{ .reg .u64 tmp; cvta.to.shared.u64 tmp, %1; cvt.u32.u64 %0, tmp; }"
        : "=r"(a) : "l"(p));
    return a;
}

__global__ __launch_bounds__(256, 1) __cluster_dims__(2, 1, 1)
void rnn_kernel(const float* __restrict__ Wh_f,
                const float* __restrict__ Wh_b,
                float* __restrict__ out)
{
    __shared__ __align__(16) float sH[2][H_SZ];   // full h vector, double-buffered
    __shared__ float sRed[128];                   // k-partials from kh=1
    __shared__ __align__(8) unsigned long long sBar;

    const int t     = threadIdx.x;
    const int rank  = blockIdx.x & 1;      // j-half owned by this CTA
    const int c     = blockIdx.x >> 1;
    const int dir   = c >> 5;
    const int b     = c & 31;
    const int kh    = t >> 7;
    const int jl    = t & 127;
    const int jglob = rank * 128 + jl;

    const float* Wh = dir ? Wh_b : Wh_f;

    unsigned long long w2[64];
    #pragma unroll
    for (int ii = 0; ii < 64; ++ii)
        w2[ii] = pack2(Wh[(kh * 128 + 2*ii + 0) * H_SZ + jglob],
                       Wh[(kh * 128 + 2*ii + 1) * H_SZ + jglob]);

    sH[0][t] = 0.0f;
    const uint32_t barLocal = smem_u32(&sBar);
    const uint32_t shBase   = smem_u32(&sH[0][0]);
    if (t == 0)
        asm volatile("mbarrier.init.shared.b64 [%0], %1;" :: "r"(barLocal), "r"(1) : "memory");
    __syncthreads();
    asm volatile("barrier.cluster.arrive.aligned;" ::: "memory");
    asm volatile("barrier.cluster.wait.aligned;"   ::: "memory");

    uint32_t peerBar, peerSh;
    {
        uint32_t pr = rank ^ 1;
        asm("mapa.shared::cluster.u32 %0, %1, %2;" : "=r"(peerBar) : "r"(barLocal), "r"(pr));
        asm("mapa.shared::cluster.u32 %0, %1, %2;" : "=r"(peerSh)  : "r"(shBase),   "r"(pr));
    }

    // s-major xp rows: [dir][sx*32 + b][j]
    const float* xp_dir   = g_xp + (size_t)dir * 65536u * 256u + (size_t)b * 256u + jglob;
    float*       out_base = out + (size_t)b * S_SZ * 512 + dir * 256 + jglob;
    const unsigned* progp = &g_prog[dir];

    int sx = dir ? (S_SZ - 1) : 0;
    const int sstep = dir ? -1 : 1;
    unsigned avail = 0;                    // cached prefix counter

    float xpv = 0.0f;
    if (t < 128) {
        unsigned need = (unsigned)(dir ? (S_SZ - 1 - sx) : sx) + 1u;   // = 1
        if (avail < need) {
            do {
                asm volatile("ld.acquire.gpu.global.u32 %0, [%1];"
                             : "=r"(avail) : "l"(progp) : "memory");
                if (avail < need) __nanosleep(128);
            } while (avail < need);
        }
        xpv = __ldg(xp_dir + (size_t)sx * 8192u);
    }

    for (int s = 0; s < S_SZ; ++s) {
        if (t == 0 && s + 1 < S_SZ)
            asm volatile("mbarrier.arrive.expect_tx.shared.b64 _, [%0], %1;"
                         :: "r"(barLocal), "r"(512) : "memory");

        // prefetch next step's xp (gated on producer progress; fast path = 2 ops)
        float xpn = 0.0f;
        if (t < 128 && s + 1 < S_SZ) {
            int nsx = sx + sstep;
            unsigned need = (unsigned)(dir ? (S_SZ - 1 - nsx) : nsx) + 1u;
            if (avail < need) {
                do {
                    asm volatile("ld.acquire.gpu.global.u32 %0, [%1];"
                                 : "=r"(avail) : "l"(progp) : "memory");
                    if (avail < need) __nanosleep(128);
                } while (avail < need);
            }
            xpn = __ldg(xp_dir + (size_t)nsx * 8192u);
        }

        // partial GEMV over this thread's k-half (packed f32x2 FMA)
        const float* hb = sH[s & 1] + (kh << 7);
        unsigned long long p0 = 0ull, p1 = 0ull;
        #pragma unroll
        for (int q = 0; q < 32; ++q) {
            ulonglong2 hv = *(const ulonglong2*)(hb + (q << 2));  // broadcast
            FMA2(p0, hv.x, w2[2*q + 0]);
            FMA2(p1, hv.y, w2[2*q + 1]);
        }
        float a0, a1, a2, a3;
        unpack2(p0, a0, a1);
        unpack2(p1, a2, a3);
        float acc = (a0 + a1) + (a2 + a3);

        if (kh) sRed[jl] = acc;
        __syncthreads();

        if (t < 128) {
            float hnew = fast_tanh(acc + sRed[jl] + xpv);
            int nb = (s + 1) & 1;
            sH[nb][jglob] = hnew;                      // local copy
            out_base[(size_t)sx * 512] = hnew;         // output (coalesced)
            if (s + 1 < S_SZ) {
                uint32_t dst = peerSh + (uint32_t)(nb * 256 + jglob) * 4u;
                asm volatile(
                    "st.async.shared::cluster.mbarrier::complete_tx::bytes.u32 [%0], %1, [%2];"
                    :: "r"(dst), "r"(__float_as_uint(hnew)), "r"(peerBar) : "memory");
            }
        }
        xpv = xpn;
        __syncthreads();   // local sH[nb] writes visible; sRed safe for reuse

        if (s + 1 < S_SZ) {
            uint32_t parity = (uint32_t)(s & 1);
            asm volatile(
                "{\n\t.reg .pred P;\n\t"
                "WL_%=:\n\t"
                "mbarrier.try_wait.parity.acquire.cluster.shared::cta.b64 P, [%0], %1, 0x989680;\n\t"
                "@!P bra WL_%=;\n\t}"
                :: "r"(barLocal), "r"(parity) : "memory");
        }
        sx += sstep;
    }
}

// ---------------------------------------------------------------------------
extern "C" void kernel_launch(void* const* d_in, const int* in_sizes, int n_in,
                              void* d_out, int out_size)
{
    const float* x    = (const float*)d_in[0];
    const float* Wx_f = (const float*)d_in[1];
    const float* Wh_f = (const float*)d_in[2];
    const float* b_f  = (const float*)d_in[3];
    const float* Wx_b = (const float*)d_in[4];
    const float* Wh_b = (const float*)d_in[5];
    const float* b_b  = (const float*)d_in[6];
    float* out = (float*)d_out;

    static cudaStream_t s_xp = nullptr;
    static cudaEvent_t evF = nullptr, evJ = nullptr;
    if (s_xp == nullptr) {
        cudaStreamCreateWithFlags(&s_xp, cudaStreamNonBlocking);
        cudaEventCreateWithFlags(&evF, cudaEventDisableTiming);
        cudaEventCreateWithFlags(&evJ, cudaEventDisableTiming);
        cudaFuncSetAttribute(xp_kernel, cudaFuncAttributeMaxDynamicSharedMemorySize,
                             XP_SMEM_BYTES);
    }

    // reset progress counters, then fork: xp (producer) || rnn (consumer)
    reset_kernel<<<1, 32>>>();
    cudaEventRecord(evF, 0);
    cudaStreamWaitEvent(s_xp, evF, 0);
    xp_kernel<<<2 * S_SZ, 128, XP_SMEM_BYTES, s_xp>>>(x, Wx_f, b_f, Wx_b, b_b);
    cudaEventRecord(evJ, s_xp);
    rnn_kernel<<<128, 256>>>(Wh_f, Wh_b, out);
    cudaStreamWaitEvent(0, evJ, 0);
}